// round 15
// baseline (speedup 1.0000x reference)
#include <cuda_runtime.h>
#include <cstdint>

// y2[a,d,z] = sum_c ( sum_b x1[a,b,z]*x0[b,c,z] ) * x2[c,d,z]
// All tensors (32,32,32768) fp32 row-major, z contiguous. Lane = one f32x2 z-pair.
// R15 = R14 (rotated reduction order, 128thr/4 warps, 8a x 8c tile, y1 64KB
// smem, 2 blocks/SM, distance-1 reg double-buffer on bv/xv)
// + NEW: zero-register prefetch.global.L1 for the av stream at DISTANCE 2.
// Rotation made av rows warp-unique (4 misses in flight) but left av at
// distance-0 (~600cyc exposed). L1 prefetch 2 steps (~1260cyc) ahead turns
// the consuming LDG into an L1 hit. bv/xv keep their 1-step register lead
// (L2-resident via rotation-desynced block sharing).

#define ZH   16384          // z-pairs (f32x2)
#define SDIM 32

using u64 = unsigned long long;

__device__ __forceinline__ u64 ffma2(u64 a, u64 b, u64 c) {
    u64 d;
    asm("fma.rn.f32x2 %0, %1, %2, %3;" : "=l"(d) : "l"(a), "l"(b), "l"(c));
    return d;
}

__device__ __forceinline__ void pf_l1(const u64* ptr) {
    asm volatile("prefetch.global.L1 [%0];" :: "l"(ptr));
}

__global__ void __launch_bounds__(128, 2)
einnet_fused11_kernel(const u64* __restrict__ x0,
                      const u64* __restrict__ x1,
                      const u64* __restrict__ x2,
                      u64* __restrict__ out)
{
    // y1 tile: [a(8)][c(32)][lane(32)] u64 = 64KB
    extern __shared__ u64 y1s[];

    const int lane = threadIdx.x & 31;
    const int w    = threadIdx.x >> 5;            // 0..3
    const int cg   = w * 8;                       // c/d stripe base (output cols)
    const int abas = blockIdx.x * 8;              // a-group base (0,8,16,24)
    const int p    = blockIdx.y * 32 + lane;      // global z-pair
    const int rot  = (w + blockIdx.x) & 3;        // reduction-order rotation

    u64 acc[8][8];
    #pragma unroll
    for (int i = 0; i < 8; i++)
        #pragma unroll
        for (int j = 0; j < 8; j++) acc[i][j] = 0ull;

    // ---------------- Pass 1: y1[a,c] = sum_b x1[a,b] * x0[b,c] ----------------
    const u64* __restrict__ Ap = x1 + (size_t)(abas * SDIM) * ZH + p;
    const u64* __restrict__ Bp = x0 + (size_t)cg * ZH + p;

    u64 bv[2][8];
    {   // initial load: chunk `rot`, step 0  (row = rot*8)
        const u64* Br = Bp + (size_t)(rot * 8) * SDIM * ZH;
        const u64* Ar = Ap + (size_t)(rot * 8) * ZH;
        #pragma unroll
        for (int j = 0; j < 8; j++) bv[0][j] = Br[(size_t)j * ZH];
        // warm L1 for the first two steps' av rows
        #pragma unroll
        for (int i = 0; i < 8; i++) { pf_l1(Ar + (size_t)(i * SDIM) * ZH);
                                      pf_l1(Ar + (size_t)(i * SDIM + 1) * ZH); }
    }

    for (int kk = 0; kk < 4; kk++) {              // 4 chunks (runtime rot base)
        const int ch  = (rot + kk) & 3;
        const int chn = (rot + kk + 1) & 3;
        const u64* __restrict__ Ar  = Ap + (size_t)(ch  * 8) * ZH;         // av rows
        const u64* __restrict__ Arn = Ap + (size_t)(chn * 8) * ZH;         // next chunk
        const u64* __restrict__ Br  = Bp + (size_t)(ch  * 8) * SDIM * ZH;  // bv rows
        const u64* __restrict__ Brn = Bp + (size_t)(chn * 8) * SDIM * ZH;

        #pragma unroll
        for (int s = 0; s < 8; s++) {             // compile-time steps
            const int cur = s & 1;
            if (s + 1 < 8) {
                #pragma unroll
                for (int j = 0; j < 8; j++)
                    bv[cur ^ 1][j] = Br[(size_t)((s + 1) * SDIM + j) * ZH];
            } else if (kk + 1 < 4) {
                #pragma unroll
                for (int j = 0; j < 8; j++)
                    bv[cur ^ 1][j] = Brn[(size_t)j * ZH];
            }

            // distance-2 L1 prefetch of av (zero registers)
            if (s + 2 < 8) {
                #pragma unroll
                for (int i = 0; i < 8; i++)
                    pf_l1(Ar + (size_t)(i * SDIM + s + 2) * ZH);
            } else if (kk + 1 < 4) {
                #pragma unroll
                for (int i = 0; i < 8; i++)
                    pf_l1(Arn + (size_t)(i * SDIM + (s + 2 - 8)) * ZH);
            }

            u64 av[8];
            #pragma unroll
            for (int i = 0; i < 8; i++) av[i] = Ar[(size_t)(i * SDIM + s) * ZH];

            #pragma unroll
            for (int i = 0; i < 8; i++)
                #pragma unroll
                for (int j = 0; j < 8; j++)
                    acc[i][j] = ffma2(av[i], bv[cur][j], acc[i][j]);
        }
    }

    // store y1 stripe (conflict-free: lane-consecutive 8B)
    #pragma unroll
    for (int i = 0; i < 8; i++)
        #pragma unroll
        for (int j = 0; j < 8; j++)
            y1s[(i * SDIM + cg + j) * 32 + lane] = acc[i][j];
    __syncthreads();

    // ---------------- Pass 2: y2[a,d] = sum_c y1[a,c] * x2[c,d] ----------------
    #pragma unroll
    for (int i = 0; i < 8; i++)
        #pragma unroll
        for (int j = 0; j < 8; j++) acc[i][j] = 0ull;

    const u64* __restrict__ Cp = x2 + (size_t)cg * ZH + p;

    u64 xv[2][8];
    {
        const u64* Cr = Cp + (size_t)(rot * 8) * SDIM * ZH;
        #pragma unroll
        for (int j = 0; j < 8; j++) xv[0][j] = Cr[(size_t)j * ZH];
    }

    for (int kk = 0; kk < 4; kk++) {
        const int ch  = (rot + kk) & 3;
        const int chn = (rot + kk + 1) & 3;
        const u64* __restrict__ Cr  = Cp + (size_t)(ch  * 8) * SDIM * ZH;
        const u64* __restrict__ Crn = Cp + (size_t)(chn * 8) * SDIM * ZH;
        const u64* __restrict__ Yr  = y1s + (size_t)(ch * 8) * 32;   // y1 rows (c dim)

        #pragma unroll
        for (int s = 0; s < 8; s++) {
            const int cur = s & 1;
            if (s + 1 < 8) {
                #pragma unroll
                for (int j = 0; j < 8; j++)
                    xv[cur ^ 1][j] = Cr[(size_t)((s + 1) * SDIM + j) * ZH];
            } else if (kk + 1 < 4) {
                #pragma unroll
                for (int j = 0; j < 8; j++)
                    xv[cur ^ 1][j] = Crn[(size_t)j * ZH];
            }

            u64 yv[8];
            #pragma unroll
            for (int i = 0; i < 8; i++)
                yv[i] = Yr[((size_t)i * SDIM + s) * 32 + lane];   // smem, conflict-free

            #pragma unroll
            for (int i = 0; i < 8; i++)
                #pragma unroll
                for (int j = 0; j < 8; j++)
                    acc[i][j] = ffma2(yv[i], xv[cur][j], acc[i][j]);
        }
    }

    u64* __restrict__ Op = out + (size_t)(abas * SDIM + cg) * ZH + p;
    #pragma unroll
    for (int i = 0; i < 8; i++)
        #pragma unroll
        for (int j = 0; j < 8; j++)
            Op[(size_t)(i * SDIM + j) * ZH] = acc[i][j];
}

extern "C" void kernel_launch(void* const* d_in, const int* in_sizes, int n_in,
                              void* d_out, int out_size)
{
    (void)in_sizes; (void)n_in; (void)out_size;
    const u64* x0 = (const u64*)d_in[0];   // (b, c, Z)
    const u64* x1 = (const u64*)d_in[1];   // (a, b, Z)
    const u64* x2 = (const u64*)d_in[2];   // (c, d, Z)
    u64* out = (u64*)d_out;

    constexpr int SMEM_BYTES = 8 * SDIM * 32 * 8;   // 65536 = 64KB
    cudaFuncSetAttribute(einnet_fused11_kernel,
                         cudaFuncAttributeMaxDynamicSharedMemorySize, SMEM_BYTES);

    // z-tile slow dim: the 4 a-group blocks of one z-tile are co-resident
    // (2 per SM) and share x0/x2 slices in L2.
    dim3 grid(4, ZH / 32);
    einnet_fused11_kernel<<<grid, 128, SMEM_BYTES>>>(x0, x1, x2, out);
}